// round 14
// baseline (speedup 1.0000x reference)
#include <cuda_runtime.h>

// MFNet two-layer MFConv — project-then-aggregate (R13) with an issue-lean
// projection GEMV: even/odd-feature accumulator splitting lets fma.rn.f32x2
// consume naturally-packed (x_2f, x_2f+1) pairs from LDG.128 (zero pack MOVs;
// weights pre-packed feature-pairwise). R13's proj1 spent ~57us on LDG issue
// alone (640 LDG + 1024 MOV per warp); this form is 384 LDG + 0 MOV.
// Replay-safe: g_deg restored by k_place, g_total/g_mcnt by k_fused2.

#define NMAX 100352
#define EMAX 1664000
#define FIN  128
#define FH   32
#define FO   64
#define DMAX 10
#define TPB  256
#define GRP  8
#define NW1  (11 * FIN * FH)        // 45056
#define NW2  (11 * FH * FO)         // 22528
#define NWF  (11 * (FIN / 2) * FH)  // 22528 feature-paired entries

typedef unsigned long long u64;

// scratch (static __device__ — no allocations allowed)
__device__ int g_deg[NMAX];      // INVARIANT zero at entry (restored: k_place)
__device__ int g_total;          // INVARIANT zero at entry (restored: k_fused2)
__device__ int g_mcnt;           // INVARIANT zero at entry (restored: k_fused2)
__device__ int g_mlist[NMAX];
__device__ int g_rowbeg[NMAX];
__device__ int g_rowend[NMAX];
__device__ int g_cursor[NMAX];
__device__ int g_csr[EMAX];
__device__ __align__(16) float g_h[NMAX * FH];      // 12.8 MB
__device__ __align__(16) float g_y10[NMAX * FH];    // x @ W1[10]
__device__ __align__(16) float g_r10[NMAX * FH];    // x @ Wr1[10]
__device__ __align__(16) u64 g_Wp1[NW1];            // (W1,Wr1) interleaved (minority path)
__device__ __align__(16) u64 g_Wf1[NWF];            // W1 feature-paired (2f,2f+1)
__device__ __align__(16) u64 g_Wfr1[NWF];           // Wr1 feature-paired
__device__ __align__(16) u64 g_Wp2[NW2];            // (W2,Wr2) interleaved

__device__ __forceinline__ u64 pack2(float lo, float hi) {
    u64 r; asm("mov.b64 %0, {%1, %2};" : "=l"(r) : "f"(lo), "f"(hi)); return r;
}
__device__ __forceinline__ void unpack2(u64 v, float& lo, float& hi) {
    asm("mov.b64 {%0, %1}, %2;" : "=f"(lo), "=f"(hi) : "l"(v));
}
__device__ __forceinline__ void fma2(u64& d, u64 a, u64 b) {
    asm("fma.rn.f32x2 %0, %1, %2, %0;" : "+l"(d) : "l"(a), "l"(b));
}

// ------------------------------------------- [0] degree histogram (deg==0 in)
__global__ void k_hist(const int* __restrict__ ei, int E, int N) {
    int e = blockIdx.x * blockDim.x + threadIdx.x;
    if (e >= E) return;
    int d = __ldg(ei + E + e);
    if ((unsigned)d < (unsigned)N) atomicAdd(g_deg + d, 1);
}

// ---------------- [1] slice allocation (warp-aggregated atomic) + weight pack
__global__ void k_alloc(const float* __restrict__ W1, const float* __restrict__ Wr1,
                        const float* __restrict__ W2, const float* __restrict__ Wr2,
                        int N) {
    int i = blockIdx.x * blockDim.x + threadIdx.x;
    if (i < NW1) g_Wp1[i] = pack2(__ldg(W1 + i), __ldg(Wr1 + i));
    if (i < NW2) g_Wp2[i] = pack2(__ldg(W2 + i), __ldg(Wr2 + i));
    if (i < NWF) {
        int d = i / ((FIN / 2) * FH);
        int rem = i - d * (FIN / 2) * FH;
        int f2 = rem / FH, o = rem - f2 * FH;
        int idx = d * FIN * FH + (2 * f2) * FH + o;
        g_Wf1[i]  = pack2(__ldg(W1 + idx),  __ldg(W1 + idx + FH));
        g_Wfr1[i] = pack2(__ldg(Wr1 + idx), __ldg(Wr1 + idx + FH));
    }

    int lane = threadIdx.x & 31;
    int d = (i < N) ? g_deg[i] : 0;
    int incl = d;
#pragma unroll
    for (int off = 1; off < 32; off <<= 1) {
        int v = __shfl_up_sync(0xffffffffu, incl, off);
        if (lane >= off) incl += v;
    }
    int wtot = __shfl_sync(0xffffffffu, incl, 31);
    int base = 0;
    if (lane == 31) base = atomicAdd(&g_total, wtot);
    base = __shfl_sync(0xffffffffu, base, 31);
    int beg = base + incl - d;
    if (i < N) { g_rowbeg[i] = beg; g_rowend[i] = beg + d; g_cursor[i] = beg; }
}

// ------- [2] CSR placement + minority list; restores g_deg=0 entry invariant
__global__ void k_place(const int* __restrict__ ei, int E, int N) {
    int e = blockIdx.x * blockDim.x + threadIdx.x;
    if (e < N) {
        g_deg[e] = 0;                        // consumed by k_alloc; restore
        if (g_rowend[e] - g_rowbeg[e] < DMAX)
            g_mlist[atomicAdd(&g_mcnt, 1)] = e;
    }
    if (e >= E) return;
    int s = __ldg(ei + e);
    int d = __ldg(ei + E + e);
    if ((unsigned)s >= (unsigned)N || (unsigned)d >= (unsigned)N) return;
    int pos = atomicAdd(g_cursor + d, 1);
    if (pos < EMAX) g_csr[pos] = s;
}

// --------- [3] bucket-10 projection (PROFILED SLOT), GRP=8, even/odd split
// acc.lo accumulates even-feature partials, acc.hi odd-feature; a-operand is
// a naturally packed ulonglong2 from the x row (LDG.128, broadcast, no MOVs).
__global__ __launch_bounds__(TPB) void k_proj1(const float* __restrict__ x, int N) {
    int gw = (blockIdx.x * blockDim.x + threadIdx.x) >> 5;
    int lane = threadIdx.x & 31;
    int base = gw * GRP;
    if (base >= N) return;

    const ulonglong2* xrow[GRP];
#pragma unroll
    for (int g = 0; g < GRP; g++) {
        int n = base + g;
        xrow[g] = reinterpret_cast<const ulonglong2*>(x + (size_t)min(n, N - 1) * FIN);
    }
    u64 accy[GRP], accr[GRP];
#pragma unroll
    for (int g = 0; g < GRP; g++) { accy[g] = 0ull; accr[g] = 0ull; }

    const u64* Wy = g_Wf1  + DMAX * (FIN / 2) * FH;
    const u64* Wr = g_Wfr1 + DMAX * (FIN / 2) * FH;
#pragma unroll 4
    for (int f4 = 0; f4 < FIN / 4; f4++) {      // features 4f4 .. 4f4+3
        u64 wy0 = __ldg(Wy + (2 * f4 + 0) * FH + lane);
        u64 wy1 = __ldg(Wy + (2 * f4 + 1) * FH + lane);
        u64 wr0 = __ldg(Wr + (2 * f4 + 0) * FH + lane);
        u64 wr1 = __ldg(Wr + (2 * f4 + 1) * FH + lane);
#pragma unroll
        for (int g = 0; g < GRP; g++) {
            ulonglong2 xp = __ldg(xrow[g] + f4);  // (x4f,x4f+1),(x4f+2,x4f+3)
            fma2(accy[g], xp.x, wy0);
            fma2(accr[g], xp.x, wr0);
            fma2(accy[g], xp.y, wy1);
            fma2(accr[g], xp.y, wr1);
        }
    }
#pragma unroll
    for (int g = 0; g < GRP; g++) {
        int n = base + g;
        if (n < N) {
            float e, o;
            unpack2(accy[g], e, o);
            g_y10[(size_t)n * FH + lane] = e + o;
            unpack2(accr[g], e, o);
            g_r10[(size_t)n * FH + lane] = e + o;
        }
    }
}

// ---------- [4] majority aggregation (deg>=10): gather 128B y10 rows (1 wf/e)
__global__ __launch_bounds__(TPB) void k_agg1(const float* __restrict__ b1, int N) {
    int t = blockIdx.x * blockDim.x + threadIdx.x;
    int n = t >> 5, lane = t & 31;
    if (n >= N) return;
    int beg = g_rowbeg[n], end = g_rowend[n];
    if (end - beg < DMAX) return;            // minority handled by k_minor1
    float hs = 0.f;
    int j = beg;
    for (; j + 4 <= end; j += 4) {
        int s0 = __ldg(g_csr + j + 0);
        int s1 = __ldg(g_csr + j + 1);
        int s2 = __ldg(g_csr + j + 2);
        int s3 = __ldg(g_csr + j + 3);
        hs += __ldg(g_y10 + (size_t)s0 * FH + lane)
            + __ldg(g_y10 + (size_t)s1 * FH + lane)
            + __ldg(g_y10 + (size_t)s2 * FH + lane)
            + __ldg(g_y10 + (size_t)s3 * FH + lane);
    }
    for (; j < end; j++) {
        int s = __ldg(g_csr + j);
        hs += __ldg(g_y10 + (size_t)s * FH + lane);
    }
    hs += __ldg(b1 + DMAX * FH + lane) + g_r10[(size_t)n * FH + lane];
    g_h[(size_t)n * FH + lane] = fmaxf(hs, 0.f);
}

// -------------- [5] minority (deg<10): wide x gather + per-bucket matvec
__global__ __launch_bounds__(TPB) void k_minor1(const float* __restrict__ x,
                                                const float* __restrict__ b1) {
    int gw = (blockIdx.x * blockDim.x + threadIdx.x) >> 5;
    int lane = threadIdx.x & 31;
    if (gw >= g_mcnt) return;
    int n = g_mlist[gw];
    int beg = g_rowbeg[n], end = g_rowend[n];
    int d = min(end - beg, DMAX);

    float a0 = 0.f, a1 = 0.f, a2 = 0.f, a3 = 0.f;
    for (int j = beg; j < end; j++) {
        int s = __ldg(g_csr + j);
        float4 v = *reinterpret_cast<const float4*>(x + (size_t)s * FIN + lane * 4);
        a0 += v.x; a1 += v.y; a2 += v.z; a3 += v.w;
    }
    float4 xr = *reinterpret_cast<const float4*>(x + (size_t)n * FIN + lane * 4);

    const u64* Wp = g_Wp1 + d * FIN * FH;
    u64 acc = pack2(__ldg(b1 + d * FH + lane), 0.f);
#pragma unroll
    for (int q = 0; q < 32; q++) {
        float h0 = __shfl_sync(0xffffffffu, a0, q);
        float h1 = __shfl_sync(0xffffffffu, a1, q);
        float h2 = __shfl_sync(0xffffffffu, a2, q);
        float h3 = __shfl_sync(0xffffffffu, a3, q);
        float x0 = __shfl_sync(0xffffffffu, xr.x, q);
        float x1 = __shfl_sync(0xffffffffu, xr.y, q);
        float x2 = __shfl_sync(0xffffffffu, xr.z, q);
        float x3 = __shfl_sync(0xffffffffu, xr.w, q);
        int f = q * 4;
        fma2(acc, pack2(h0, x0), __ldg(Wp + (f + 0) * FH + lane));
        fma2(acc, pack2(h1, x1), __ldg(Wp + (f + 1) * FH + lane));
        fma2(acc, pack2(h2, x2), __ldg(Wp + (f + 2) * FH + lane));
        fma2(acc, pack2(h3, x3), __ldg(Wp + (f + 3) * FH + lane));
    }
    float lo, hi; unpack2(acc, lo, hi);
    g_h[(size_t)n * FH + lane] = fmaxf(lo + hi, 0.f);
}

// --- [6] layer 2: fused gather + transform (single pass, dual-half accs);
//         restores g_total=0 and g_mcnt=0 entry invariants
__global__ __launch_bounds__(TPB) void k_fused2(const float* __restrict__ b2,
                                                float* __restrict__ out, int N) {
    if (blockIdx.x == 0 && threadIdx.x == 0) { g_total = 0; g_mcnt = 0; }
    __shared__ __align__(16) u64 sh[TPB / 32][GRP * FH];   // 8 warps x 2KB
    int gw = (blockIdx.x * blockDim.x + threadIdx.x) >> 5;
    int lane = threadIdx.x & 31;
    u64* hh = sh[threadIdx.x >> 5];
    int base = gw * GRP;
    if (base >= N) return;

    int dg[GRP];
#pragma unroll
    for (int g = 0; g < GRP; g++) {
        int n = base + g;
        float hs = 0.f, hn = 0.f;
        int d = -1;
        if (n < N) {
            int beg = g_rowbeg[n], end = g_rowend[n];
            d = min(end - beg, DMAX);
            int j = beg;
            for (; j + 4 <= end; j += 4) {
                int s0 = __ldg(g_csr + j + 0);
                int s1 = __ldg(g_csr + j + 1);
                int s2 = __ldg(g_csr + j + 2);
                int s3 = __ldg(g_csr + j + 3);
                hs += g_h[(size_t)s0 * FH + lane] + g_h[(size_t)s1 * FH + lane]
                    + g_h[(size_t)s2 * FH + lane] + g_h[(size_t)s3 * FH + lane];
            }
            for (; j < end; j++) {
                int s = __ldg(g_csr + j);
                hs += g_h[(size_t)s * FH + lane];
            }
            hn = g_h[(size_t)n * FH + lane];
        }
        dg[g] = d;
        hh[g * FH + lane] = pack2(hs, hn);
    }
    __syncwarp();

    bool all10 = true;
#pragma unroll
    for (int g = 0; g < GRP; g++) all10 = all10 && (dg[g] == DMAX);

    u64 accA[GRP], accB[GRP];
#pragma unroll
    for (int g = 0; g < GRP; g++) {
        accA[g] = pack2((dg[g] >= 0) ? __ldg(b2 + dg[g] * FO + lane) : 0.f, 0.f);
        accB[g] = pack2((dg[g] >= 0) ? __ldg(b2 + dg[g] * FO + 32 + lane) : 0.f, 0.f);
    }

    const u64* W10 = g_Wp2 + DMAX * FH * FO;
    if (all10) {
#pragma unroll 4
        for (int j2 = 0; j2 < FH / 2; j2++) {
            u64 w00 = __ldg(W10 + (2 * j2 + 0) * FO + lane);
            u64 w01 = __ldg(W10 + (2 * j2 + 0) * FO + 32 + lane);
            u64 w10 = __ldg(W10 + (2 * j2 + 1) * FO + lane);
            u64 w11 = __ldg(W10 + (2 * j2 + 1) * FO + 32 + lane);
#pragma unroll
            for (int g = 0; g < GRP; g++) {
                ulonglong2 hp = *reinterpret_cast<const ulonglong2*>(hh + g * FH + 2 * j2);
                fma2(accA[g], hp.x, w00);
                fma2(accB[g], hp.x, w01);
                fma2(accA[g], hp.y, w10);
                fma2(accB[g], hp.y, w11);
            }
        }
    } else {
#pragma unroll 4
        for (int j2 = 0; j2 < FH / 2; j2++) {
            u64 w00 = __ldg(W10 + (2 * j2 + 0) * FO + lane);
            u64 w01 = __ldg(W10 + (2 * j2 + 0) * FO + 32 + lane);
            u64 w10 = __ldg(W10 + (2 * j2 + 1) * FO + lane);
            u64 w11 = __ldg(W10 + (2 * j2 + 1) * FO + 32 + lane);
#pragma unroll
            for (int g = 0; g < GRP; g++) {
                if (dg[g] != DMAX) continue;
                ulonglong2 hp = *reinterpret_cast<const ulonglong2*>(hh + g * FH + 2 * j2);
                fma2(accA[g], hp.x, w00);
                fma2(accB[g], hp.x, w01);
                fma2(accA[g], hp.y, w10);
                fma2(accB[g], hp.y, w11);
            }
        }
#pragma unroll
        for (int g = 0; g < GRP; g++) {
            if (dg[g] < 0 || dg[g] == DMAX) continue;
            const u64* Wp = g_Wp2 + dg[g] * FH * FO;
#pragma unroll 8
            for (int j = 0; j < FH; j++) {
                u64 hv = hh[g * FH + j];
                fma2(accA[g], hv, __ldg(Wp + j * FO + lane));
                fma2(accB[g], hv, __ldg(Wp + j * FO + 32 + lane));
            }
        }
    }
#pragma unroll
    for (int g = 0; g < GRP; g++) {
        int n = base + g;
        if (dg[g] >= 0) {
            float lo, hi;
            unpack2(accA[g], lo, hi);
            out[(size_t)n * FO + lane] = lo + hi;
            unpack2(accB[g], lo, hi);
            out[(size_t)n * FO + 32 + lane] = lo + hi;
        }
    }
}

// ============================================================================
extern "C" void kernel_launch(void* const* d_in, const int* in_sizes, int n_in,
                              void* d_out, int out_size) {
    const float* x   = (const float*)d_in[0];
    const int*   ei  = (const int*)d_in[1];     // int32 (JAX x64 disabled)
    const float* W1  = (const float*)d_in[2];
    const float* b1  = (const float*)d_in[3];
    const float* Wr1 = (const float*)d_in[4];
    const float* W2  = (const float*)d_in[5];
    const float* b2  = (const float*)d_in[6];
    const float* Wr2 = (const float*)d_in[7];
    float* out = (float*)d_out;

    int N = in_sizes[0] / FIN;
    int E = in_sizes[1] / 2;
    if (N > NMAX) N = NMAX;
    if (E > EMAX) E = EMAX;

    int nb    = (N + TPB - 1) / TPB;           // covers NW1=45056 too
    int egrid = (E + TPB - 1) / TPB;
    int nwarps = (N + GRP - 1) / GRP;
    int ggrid = (nwarps * 32 + TPB - 1) / TPB;
    int wgrid = (N * 32 + TPB - 1) / TPB;

    k_hist  <<<egrid, TPB>>>(ei, E, N);                // 0
    k_alloc <<<nb,    TPB>>>(W1, Wr1, W2, Wr2, N);     // 1
    k_place <<<egrid, TPB>>>(ei, E, N);                // 2
    k_proj1 <<<ggrid, TPB>>>(x, N);                    // 3  <- profiled
    k_agg1  <<<wgrid, TPB>>>(b1, N);                   // 4
    k_minor1<<<wgrid, TPB>>>(x, b1);                   // 5
    k_fused2<<<ggrid, TPB>>>(b2, out, N);              // 6
}

// round 16
// speedup vs baseline: 1.0792x; 1.0792x over previous
#include <cuda_runtime.h>

// MFNet two-layer MFConv — project-then-aggregate, with the layer-1 projection
// written as a real smem-tiled register-blocked GEMM:
//   [y10|r10] = x[N,128] @ [W1[10]|Wr1[10]]  (u64 (W,Wr)-pair weights, f32x2)
// R14 post-mortem: warp-per-8-nodes GEMV was latency-bound at 22.8% occ;
// 4x4 register tiles give 16 FFMA2 : 6 LDS per k-step at ~64% occupancy.
// Majority (deg>=10, ~96%) aggregates 128B y10 rows; minority via compacted
// list + wide x gather. Replay-safe: g_deg restored by k_place,
// g_total/g_mcnt by k_fused2.

#define NMAX 100352
#define EMAX 1664000
#define FIN  128
#define FH   32
#define FO   64
#define DMAX 10
#define TPB  256
#define GRP  8
#define PBN  128                    // projg: nodes per block
#define PBK  32                     // projg: k-chunk
#define NW1  (11 * FIN * FH)        // 45056
#define NW2  (11 * FH * FO)         // 22528

typedef unsigned long long u64;

// scratch (static __device__ — no allocations allowed)
__device__ int g_deg[NMAX];      // INVARIANT zero at entry (restored: k_place)
__device__ int g_total;          // INVARIANT zero at entry (restored: k_fused2)
__device__ int g_mcnt;           // INVARIANT zero at entry (restored: k_fused2)
__device__ int g_mlist[NMAX];
__device__ int g_rowbeg[NMAX];
__device__ int g_rowend[NMAX];
__device__ int g_cursor[NMAX];
__device__ int g_csr[EMAX];
__device__ __align__(16) float g_h[NMAX * FH];      // 12.8 MB
__device__ __align__(16) float g_y10[NMAX * FH];    // x @ W1[10]
__device__ __align__(16) float g_r10[NMAX * FH];    // x @ Wr1[10]
__device__ __align__(16) u64 g_Wp1[NW1];            // (W1,Wr1) interleaved
__device__ __align__(16) u64 g_Wp2[NW2];            // (W2,Wr2) interleaved

__device__ __forceinline__ u64 pack2(float lo, float hi) {
    u64 r; asm("mov.b64 %0, {%1, %2};" : "=l"(r) : "f"(lo), "f"(hi)); return r;
}
__device__ __forceinline__ void unpack2(u64 v, float& lo, float& hi) {
    asm("mov.b64 {%0, %1}, %2;" : "=f"(lo), "=f"(hi) : "l"(v));
}
__device__ __forceinline__ void fma2(u64& d, u64 a, u64 b) {
    asm("fma.rn.f32x2 %0, %1, %2, %0;" : "+l"(d) : "l"(a), "l"(b));
}

// ------------------------------------------- [0] degree histogram (deg==0 in)
__global__ void k_hist(const int* __restrict__ ei, int E, int N) {
    int e = blockIdx.x * blockDim.x + threadIdx.x;
    if (e >= E) return;
    int d = __ldg(ei + E + e);
    if ((unsigned)d < (unsigned)N) atomicAdd(g_deg + d, 1);
}

// ---------------- [1] slice allocation (warp-aggregated atomic) + weight pack
__global__ void k_alloc(const float* __restrict__ W1, const float* __restrict__ Wr1,
                        const float* __restrict__ W2, const float* __restrict__ Wr2,
                        int N) {
    int i = blockIdx.x * blockDim.x + threadIdx.x;
    if (i < NW1) g_Wp1[i] = pack2(__ldg(W1 + i), __ldg(Wr1 + i));
    if (i < NW2) g_Wp2[i] = pack2(__ldg(W2 + i), __ldg(Wr2 + i));

    int lane = threadIdx.x & 31;
    int d = (i < N) ? g_deg[i] : 0;
    int incl = d;
#pragma unroll
    for (int off = 1; off < 32; off <<= 1) {
        int v = __shfl_up_sync(0xffffffffu, incl, off);
        if (lane >= off) incl += v;
    }
    int wtot = __shfl_sync(0xffffffffu, incl, 31);
    int base = 0;
    if (lane == 31) base = atomicAdd(&g_total, wtot);
    base = __shfl_sync(0xffffffffu, base, 31);
    int beg = base + incl - d;
    if (i < N) { g_rowbeg[i] = beg; g_rowend[i] = beg + d; g_cursor[i] = beg; }
}

// ------- [2] CSR placement + minority list; restores g_deg=0 entry invariant
__global__ void k_place(const int* __restrict__ ei, int E, int N) {
    int e = blockIdx.x * blockDim.x + threadIdx.x;
    if (e < N) {
        g_deg[e] = 0;                        // consumed by k_alloc; restore
        if (g_rowend[e] - g_rowbeg[e] < DMAX)
            g_mlist[atomicAdd(&g_mcnt, 1)] = e;
    }
    if (e >= E) return;
    int s = __ldg(ei + e);
    int d = __ldg(ei + E + e);
    if ((unsigned)s >= (unsigned)N || (unsigned)d >= (unsigned)N) return;
    int pos = atomicAdd(g_cursor + d, 1);
    if (pos < EMAX) g_csr[pos] = s;
}

// ------- [3] bucket-10 projection GEMM (PROFILED SLOT)
// Block: 128 nodes x 32 channels, 256 threads, 4x4 register tiles of u64
// (y,r) accumulators. x staged pre-duplicated (x,x) in smem (padded rows);
// weights staged from g_Wp1[10]. 16 FFMA2 : 6 LDS per k-step.
__global__ __launch_bounds__(TPB) void k_projg(const float* __restrict__ x, int N) {
    __shared__ __align__(16) u64 sx[PBN][PBK + 1];   // 33.8 KB (x,x) pairs
    __shared__ __align__(16) u64 sw[PBK][FH];        // 8 KB (W,Wr) pairs
    int tx = threadIdx.x;
    int bn = blockIdx.x * PBN;
    int cg = (tx & 7) * 4;          // channel base: 0,4,..,28
    int ng = (tx >> 3) * 4;         // node base in tile: 0,4,..,124

    u64 acc[4][4];
#pragma unroll
    for (int i = 0; i < 4; i++)
#pragma unroll
        for (int j = 0; j < 4; j++) acc[i][j] = 0ull;

    const u64* W10 = g_Wp1 + DMAX * FIN * FH;

    for (int kc = 0; kc < FIN; kc += PBK) {
        // stage x: 128 rows x 32 cols; each thread 4 float4 -> 16 (x,x) u64
#pragma unroll
        for (int i = 0; i < 4; i++) {
            int li = tx + i * TPB;          // 0..1023
            int r  = li >> 3;               // row 0..127
            int c4 = li & 7;                // float4 col 0..7
            int n  = bn + r;
            float4 v = make_float4(0.f, 0.f, 0.f, 0.f);
            if (n < N)
                v = *reinterpret_cast<const float4*>(x + (size_t)n * FIN + kc + c4 * 4);
            sx[r][c4 * 4 + 0] = pack2(v.x, v.x);
            sx[r][c4 * 4 + 1] = pack2(v.y, v.y);
            sx[r][c4 * 4 + 2] = pack2(v.z, v.z);
            sx[r][c4 * 4 + 3] = pack2(v.w, v.w);
        }
        // stage weights: 32 k x 32 ch u64; each thread 4, coalesced
#pragma unroll
        for (int i = 0; i < 4; i++) {
            int li = tx + i * TPB;
            int k = li >> 5, c = li & 31;
            sw[k][c] = __ldg(W10 + (size_t)(kc + k) * FH + c);
        }
        __syncthreads();

#pragma unroll
        for (int k = 0; k < PBK; k++) {
            u64 xv[4], wv[4];
#pragma unroll
            for (int i = 0; i < 4; i++) xv[i] = sx[ng + i][k];
#pragma unroll
            for (int j = 0; j < 4; j++) wv[j] = sw[k][cg + j];
#pragma unroll
            for (int i = 0; i < 4; i++)
#pragma unroll
                for (int j = 0; j < 4; j++) fma2(acc[i][j], xv[i], wv[j]);
        }
        __syncthreads();
    }

#pragma unroll
    for (int i = 0; i < 4; i++) {
        int n = bn + ng + i;
        if (n >= N) continue;
        float4 yv, rv;
        unpack2(acc[i][0], yv.x, rv.x);
        unpack2(acc[i][1], yv.y, rv.y);
        unpack2(acc[i][2], yv.z, rv.z);
        unpack2(acc[i][3], yv.w, rv.w);
        *reinterpret_cast<float4*>(g_y10 + (size_t)n * FH + cg) = yv;
        *reinterpret_cast<float4*>(g_r10 + (size_t)n * FH + cg) = rv;
    }
}

// ---------- [4] majority aggregation (deg>=10): gather 128B y10 rows (1 wf/e)
__global__ __launch_bounds__(TPB) void k_agg1(const float* __restrict__ b1, int N) {
    int t = blockIdx.x * blockDim.x + threadIdx.x;
    int n = t >> 5, lane = t & 31;
    if (n >= N) return;
    int beg = g_rowbeg[n], end = g_rowend[n];
    if (end - beg < DMAX) return;            // minority handled by k_minor1
    float hs = 0.f;
    int j = beg;
    for (; j + 4 <= end; j += 4) {
        int s0 = __ldg(g_csr + j + 0);
        int s1 = __ldg(g_csr + j + 1);
        int s2 = __ldg(g_csr + j + 2);
        int s3 = __ldg(g_csr + j + 3);
        hs += __ldg(g_y10 + (size_t)s0 * FH + lane)
            + __ldg(g_y10 + (size_t)s1 * FH + lane)
            + __ldg(g_y10 + (size_t)s2 * FH + lane)
            + __ldg(g_y10 + (size_t)s3 * FH + lane);
    }
    for (; j < end; j++) {
        int s = __ldg(g_csr + j);
        hs += __ldg(g_y10 + (size_t)s * FH + lane);
    }
    hs += __ldg(b1 + DMAX * FH + lane) + g_r10[(size_t)n * FH + lane];
    g_h[(size_t)n * FH + lane] = fmaxf(hs, 0.f);
}

// -------------- [5] minority (deg<10): wide x gather + per-bucket matvec
__global__ __launch_bounds__(TPB) void k_minor1(const float* __restrict__ x,
                                                const float* __restrict__ b1) {
    int gw = (blockIdx.x * blockDim.x + threadIdx.x) >> 5;
    int lane = threadIdx.x & 31;
    if (gw >= g_mcnt) return;
    int n = g_mlist[gw];
    int beg = g_rowbeg[n], end = g_rowend[n];
    int d = min(end - beg, DMAX);

    float a0 = 0.f, a1 = 0.f, a2 = 0.f, a3 = 0.f;
    for (int j = beg; j < end; j++) {
        int s = __ldg(g_csr + j);
        float4 v = *reinterpret_cast<const float4*>(x + (size_t)s * FIN + lane * 4);
        a0 += v.x; a1 += v.y; a2 += v.z; a3 += v.w;
    }
    float4 xr = *reinterpret_cast<const float4*>(x + (size_t)n * FIN + lane * 4);

    const u64* Wp = g_Wp1 + d * FIN * FH;
    u64 acc = pack2(__ldg(b1 + d * FH + lane), 0.f);
#pragma unroll
    for (int q = 0; q < 32; q++) {
        float h0 = __shfl_sync(0xffffffffu, a0, q);
        float h1 = __shfl_sync(0xffffffffu, a1, q);
        float h2 = __shfl_sync(0xffffffffu, a2, q);
        float h3 = __shfl_sync(0xffffffffu, a3, q);
        float x0 = __shfl_sync(0xffffffffu, xr.x, q);
        float x1 = __shfl_sync(0xffffffffu, xr.y, q);
        float x2 = __shfl_sync(0xffffffffu, xr.z, q);
        float x3 = __shfl_sync(0xffffffffu, xr.w, q);
        int f = q * 4;
        fma2(acc, pack2(h0, x0), __ldg(Wp + (f + 0) * FH + lane));
        fma2(acc, pack2(h1, x1), __ldg(Wp + (f + 1) * FH + lane));
        fma2(acc, pack2(h2, x2), __ldg(Wp + (f + 2) * FH + lane));
        fma2(acc, pack2(h3, x3), __ldg(Wp + (f + 3) * FH + lane));
    }
    float lo, hi; unpack2(acc, lo, hi);
    g_h[(size_t)n * FH + lane] = fmaxf(lo + hi, 0.f);
}

// --- [6] layer 2: fused gather + transform (single pass, dual-half accs);
//         restores g_total=0 and g_mcnt=0 entry invariants
__global__ __launch_bounds__(TPB) void k_fused2(const float* __restrict__ b2,
                                                float* __restrict__ out, int N) {
    if (blockIdx.x == 0 && threadIdx.x == 0) { g_total = 0; g_mcnt = 0; }
    __shared__ __align__(16) u64 sh[TPB / 32][GRP * FH];   // 8 warps x 2KB
    int gw = (blockIdx.x * blockDim.x + threadIdx.x) >> 5;
    int lane = threadIdx.x & 31;
    u64* hh = sh[threadIdx.x >> 5];
    int base = gw * GRP;
    if (base >= N) return;

    int dg[GRP];
#pragma unroll
    for (int g = 0; g < GRP; g++) {
        int n = base + g;
        float hs = 0.f, hn = 0.f;
        int d = -1;
        if (n < N) {
            int beg = g_rowbeg[n], end = g_rowend[n];
            d = min(end - beg, DMAX);
            int j = beg;
            for (; j + 4 <= end; j += 4) {
                int s0 = __ldg(g_csr + j + 0);
                int s1 = __ldg(g_csr + j + 1);
                int s2 = __ldg(g_csr + j + 2);
                int s3 = __ldg(g_csr + j + 3);
                hs += g_h[(size_t)s0 * FH + lane] + g_h[(size_t)s1 * FH + lane]
                    + g_h[(size_t)s2 * FH + lane] + g_h[(size_t)s3 * FH + lane];
            }
            for (; j < end; j++) {
                int s = __ldg(g_csr + j);
                hs += g_h[(size_t)s * FH + lane];
            }
            hn = g_h[(size_t)n * FH + lane];
        }
        dg[g] = d;
        hh[g * FH + lane] = pack2(hs, hn);
    }
    __syncwarp();

    bool all10 = true;
#pragma unroll
    for (int g = 0; g < GRP; g++) all10 = all10 && (dg[g] == DMAX);

    u64 accA[GRP], accB[GRP];
#pragma unroll
    for (int g = 0; g < GRP; g++) {
        accA[g] = pack2((dg[g] >= 0) ? __ldg(b2 + dg[g] * FO + lane) : 0.f, 0.f);
        accB[g] = pack2((dg[g] >= 0) ? __ldg(b2 + dg[g] * FO + 32 + lane) : 0.f, 0.f);
    }

    const u64* W10 = g_Wp2 + DMAX * FH * FO;
    if (all10) {
#pragma unroll 4
        for (int j2 = 0; j2 < FH / 2; j2++) {
            u64 w00 = __ldg(W10 + (2 * j2 + 0) * FO + lane);
            u64 w01 = __ldg(W10 + (2 * j2 + 0) * FO + 32 + lane);
            u64 w10 = __ldg(W10 + (2 * j2 + 1) * FO + lane);
            u64 w11 = __ldg(W10 + (2 * j2 + 1) * FO + 32 + lane);
#pragma unroll
            for (int g = 0; g < GRP; g++) {
                ulonglong2 hp = *reinterpret_cast<const ulonglong2*>(hh + g * FH + 2 * j2);
                fma2(accA[g], hp.x, w00);
                fma2(accB[g], hp.x, w01);
                fma2(accA[g], hp.y, w10);
                fma2(accB[g], hp.y, w11);
            }
        }
    } else {
#pragma unroll 4
        for (int j2 = 0; j2 < FH / 2; j2++) {
            u64 w00 = __ldg(W10 + (2 * j2 + 0) * FO + lane);
            u64 w01 = __ldg(W10 + (2 * j2 + 0) * FO + 32 + lane);
            u64 w10 = __ldg(W10 + (2 * j2 + 1) * FO + lane);
            u64 w11 = __ldg(W10 + (2 * j2 + 1) * FO + 32 + lane);
#pragma unroll
            for (int g = 0; g < GRP; g++) {
                if (dg[g] != DMAX) continue;
                ulonglong2 hp = *reinterpret_cast<const ulonglong2*>(hh + g * FH + 2 * j2);
                fma2(accA[g], hp.x, w00);
                fma2(accB[g], hp.x, w01);
                fma2(accA[g], hp.y, w10);
                fma2(accB[g], hp.y, w11);
            }
        }
#pragma unroll
        for (int g = 0; g < GRP; g++) {
            if (dg[g] < 0 || dg[g] == DMAX) continue;
            const u64* Wp = g_Wp2 + dg[g] * FH * FO;
#pragma unroll 8
            for (int j = 0; j < FH; j++) {
                u64 hv = hh[g * FH + j];
                fma2(accA[g], hv, __ldg(Wp + j * FO + lane));
                fma2(accB[g], hv, __ldg(Wp + j * FO + 32 + lane));
            }
        }
    }
#pragma unroll
    for (int g = 0; g < GRP; g++) {
        int n = base + g;
        if (dg[g] >= 0) {
            float lo, hi;
            unpack2(accA[g], lo, hi);
            out[(size_t)n * FO + lane] = lo + hi;
            unpack2(accB[g], lo, hi);
            out[(size_t)n * FO + 32 + lane] = lo + hi;
        }
    }
}

// ============================================================================
extern "C" void kernel_launch(void* const* d_in, const int* in_sizes, int n_in,
                              void* d_out, int out_size) {
    const float* x   = (const float*)d_in[0];
    const int*   ei  = (const int*)d_in[1];     // int32 (JAX x64 disabled)
    const float* W1  = (const float*)d_in[2];
    const float* b1  = (const float*)d_in[3];
    const float* Wr1 = (const float*)d_in[4];
    const float* W2  = (const float*)d_in[5];
    const float* b2  = (const float*)d_in[6];
    const float* Wr2 = (const float*)d_in[7];
    float* out = (float*)d_out;

    int N = in_sizes[0] / FIN;
    int E = in_sizes[1] / 2;
    if (N > NMAX) N = NMAX;
    if (E > EMAX) E = EMAX;

    int nb    = (N + TPB - 1) / TPB;           // covers NW1=45056 too
    int egrid = (E + TPB - 1) / TPB;
    int nwarps = (N + GRP - 1) / GRP;
    int ggrid = (nwarps * 32 + TPB - 1) / TPB;
    int wgrid = (N * 32 + TPB - 1) / TPB;
    int pgrid = (N + PBN - 1) / PBN;           // 782

    k_hist  <<<egrid, TPB>>>(ei, E, N);                // 0
    k_alloc <<<nb,    TPB>>>(W1, Wr1, W2, Wr2, N);     // 1
    k_place <<<egrid, TPB>>>(ei, E, N);                // 2
    k_projg <<<pgrid, TPB>>>(x, N);                    // 3  <- profiled
    k_agg1  <<<wgrid, TPB>>>(b1, N);                   // 4
    k_minor1<<<wgrid, TPB>>>(x, b1);                   // 5
    k_fused2<<<ggrid, TPB>>>(b2, out, N);              // 6
}